// round 7
// baseline (speedup 1.0000x reference)
#include <cuda_runtime.h>
#include <cuda_bf16.h>
#include <stdint.h>

// SparseGapPerSpecies: quadratic form + warp bf16 MMA, symmetry-reduced.
//   A_s = Y_s^T diag(w/|y|^2) Y_s (symmetric) -> bf16 hi+lo
//   x'Ax = xh'A(xh+2xl) + O(2^-16)  => Q = Xh*(Ah+Al): 2 GEMM terms
//   e_atom = rowdot(Q, xh + 2xl)/|x|^2 ; energy = segment_sum
// Launch plan (ncu profiles launch #4): fuse1, off, fuse2, MAIN.

#define N_SPECIES   4
#define N_FEAT      512
#define MAX_ATOMS   100352
#define MAX_SUPPORT 1024
#define MT          128
#define NC          128
#define KC          64

__device__ __nv_bfloat16 g_Ah[N_SPECIES * N_FEAT * N_FEAT];  // [s][k][n]
__device__ __nv_bfloat16 g_Al[N_SPECIES * N_FEAT * N_FEAT];
__device__ __nv_bfloat16 g_Xh[(size_t)MAX_ATOMS * N_FEAT];   // sorted by species
__device__ __nv_bfloat16 g_Xl[(size_t)MAX_ATOMS * N_FEAT];   // holds 2*xl
__device__ float g_invn[MAX_ATOMS];
__device__ int   g_sidp[MAX_ATOMS];
__device__ float g_c[N_SPECIES * MAX_SUPPORT];
__device__ int   g_cnt[N_SPECIES];        // zero-init; k_off resets after use
__device__ int   g_off[N_SPECIES + 1];
__device__ int   g_cur[N_SPECIES];

// ---------------- PTX helpers ----------------
__device__ __forceinline__ uint32_t smem_u32(const void* p) {
    uint32_t a;
    asm("{ .reg .u64 t; cvta.to.shared.u64 t, %1; cvt.u32.u64 %0, t; }" : "=r"(a) : "l"(p));
    return a;
}
__device__ __forceinline__ void cpasync16(uint32_t dst, const void* src) {
    asm volatile("cp.async.cg.shared.global [%0], [%1], 16;" :: "r"(dst), "l"(src) : "memory");
}
#define CP_COMMIT() asm volatile("cp.async.commit_group;" ::: "memory")

__device__ __forceinline__ void ldsm_x4(uint32_t* r, uint32_t a) {
    asm volatile("ldmatrix.sync.aligned.m8n8.x4.shared.b16 {%0,%1,%2,%3}, [%4];"
                 : "=r"(r[0]), "=r"(r[1]), "=r"(r[2]), "=r"(r[3]) : "r"(a));
}
__device__ __forceinline__ void ldsm_x4t(uint32_t* r, uint32_t a) {
    asm volatile("ldmatrix.sync.aligned.m8n8.x4.trans.shared.b16 {%0,%1,%2,%3}, [%4];"
                 : "=r"(r[0]), "=r"(r[1]), "=r"(r[2]), "=r"(r[3]) : "r"(a));
}
__device__ __forceinline__ void mma16816(float* c, const uint32_t* a, const uint32_t* b) {
    asm volatile("mma.sync.aligned.m16n8k16.row.col.f32.bf16.bf16.f32 "
                 "{%0,%1,%2,%3},{%4,%5,%6,%7},{%8,%9},{%0,%1,%2,%3};"
                 : "+f"(c[0]), "+f"(c[1]), "+f"(c[2]), "+f"(c[3])
                 : "r"(a[0]), "r"(a[1]), "r"(a[2]), "r"(a[3]), "r"(b[0]), "r"(b[1]));
}
__device__ __forceinline__ uint32_t pkbf(float a, float b) {
    __nv_bfloat162 t = __floats2bfloat162_rn(a, b);
    return *(uint32_t*)&t;
}

// ---------------- launch 1: prep_c (4 pts/block) || countz ----------------
__global__ __launch_bounds__(512) void k_fuse1(const float* __restrict__ sp,
                                               const float* __restrict__ w,
                                               int n_support,
                                               const int* __restrict__ spc, int n,
                                               float* out, int n_out, int pb) {
    int bx = blockIdx.x;
    if (bx < pb) {
        // prep_c: 4 support points per block, 128 threads each
        __shared__ float r[4][4];
        int g = threadIdx.x >> 7, st = threadIdx.x & 127;
        int pt = bx * 4 + g;
        int total = N_SPECIES * n_support;
        float acc = 0.f;
        if (pt < total) {
            const float* y = sp + (size_t)pt * N_FEAT;
            #pragma unroll
            for (int t = 0; t < 4; ++t) { float v = y[st + t * 128]; acc += v * v; }
        }
        #pragma unroll
        for (int o = 16; o; o >>= 1) acc += __shfl_xor_sync(0xffffffffu, acc, o);
        if ((st & 31) == 0) r[g][st >> 5] = acc;
        __syncthreads();
        if (st == 0 && pt < total) {
            int s = pt / n_support, m = pt % n_support;
            g_c[s * MAX_SUPPORT + m] = w[pt] / (r[g][0] + r[g][1] + r[g][2] + r[g][3]);
        }
    } else {
        int i = (bx - pb) * 512 + threadIdx.x;
        if (i < n) atomicAdd(&g_cnt[spc[i]], 1);
        if (i < n_out) out[i] = 0.f;
    }
}

// ---------------- launch 2: offsets (+ reset counters for replay) ----------------
__global__ void k_off() {
    if (threadIdx.x == 0) {
        int acc = 0;
        for (int s = 0; s < N_SPECIES; ++s) {
            g_off[s] = acc; g_cur[s] = acc; acc += g_cnt[s]; g_cnt[s] = 0;
        }
        g_off[N_SPECIES] = acc;
    }
}

// ---------------- launch 3: computeA (144 blocks) || scatterX ----------------
__global__ __launch_bounds__(512) void k_fuse2(const float* __restrict__ sp, int n_support,
                                               const float* __restrict__ ps,
                                               const int* __restrict__ spc,
                                               const int* __restrict__ sids, int n) {
    int bx = blockIdx.x;
    if (bx < 36 * N_SPECIES) {
        // ---- computeA: A = Y' diag(c) Y, upper-tri 64x64 tile + mirror ----
        __shared__ float Yi[16][64];
        __shared__ float Yj[16][64];
        int s = bx / 36;
        int t = bx % 36;
        int bi = 0;
        { int rowlen = 8; while (t >= rowlen) { t -= rowlen; rowlen--; bi++; } }
        int bj = bi + t;
        int i0 = bi * 64, j0 = bj * 64;

        int tid = threadIdx.x;
        int ty = tid >> 4, tx = tid & 15;     // 32 x 16 threads, 2x4 acc
        float acc[2][4];
        #pragma unroll
        for (int a = 0; a < 2; ++a)
            #pragma unroll
            for (int b = 0; b < 4; ++b) acc[a][b] = 0.f;

        const float* Y = sp + (size_t)s * n_support * N_FEAT;
        const float* c = g_c + s * MAX_SUPPORT;

        for (int m0 = 0; m0 < n_support; m0 += 16) {
            #pragma unroll
            for (int it = 0; it < 2; ++it) {
                int idx = it * 512 + tid;
                int kk = idx >> 6, col = idx & 63;
                int m = m0 + kk;
                float yi = 0.f, yj = 0.f, cm = 0.f;
                if (m < n_support) {
                    cm = c[m];
                    yi = Y[(size_t)m * N_FEAT + i0 + col];
                    yj = Y[(size_t)m * N_FEAT + j0 + col];
                }
                Yi[kk][col] = cm * yi;
                Yj[kk][col] = yj;
            }
            __syncthreads();
            #pragma unroll
            for (int kk = 0; kk < 16; ++kk) {
                float a0 = Yi[kk][ty * 2], a1 = Yi[kk][ty * 2 + 1];
                float b[4];
                #pragma unroll
                for (int jj = 0; jj < 4; ++jj) b[jj] = Yj[kk][tx * 4 + jj];
                #pragma unroll
                for (int jj = 0; jj < 4; ++jj) { acc[0][jj] += a0 * b[jj]; acc[1][jj] += a1 * b[jj]; }
            }
            __syncthreads();
        }
        #pragma unroll
        for (int ii = 0; ii < 2; ++ii)
            #pragma unroll
            for (int jj = 0; jj < 4; ++jj) {
                int i = i0 + ty * 2 + ii;
                int j = j0 + tx * 4 + jj;
                float a = acc[ii][jj];
                __nv_bfloat16 h = __float2bfloat16(a);
                __nv_bfloat16 l = __float2bfloat16(a - __bfloat162float(h));
                size_t o = ((size_t)s * N_FEAT + i) * N_FEAT + j;
                g_Ah[o] = h; g_Al[o] = l;
                if (bi != bj) {
                    size_t om = ((size_t)s * N_FEAT + j) * N_FEAT + i;
                    g_Ah[om] = h; g_Al[om] = l;
                }
            }
    } else {
        // ---- scatterX: warp per atom; store xh and 2*xl; 1/|x|^2; sid ----
        int wid = threadIdx.x >> 5, lid = threadIdx.x & 31;
        int i = (bx - 36 * N_SPECIES) * 16 + wid;
        if (i >= n) return;
        int p;
        if (lid == 0) p = atomicAdd(&g_cur[spc[i]], 1);
        p = __shfl_sync(0xffffffffu, p, 0);

        const float4* src = (const float4*)(ps + (size_t)i * N_FEAT);
        float nrm = 0.f;
        #pragma unroll
        for (int t = 0; t < 4; ++t) {
            int v = lid + t * 32;
            float4 f = __ldg(src + v);
            nrm += f.x * f.x + f.y * f.y + f.z * f.z + f.w * f.w;
            float hx = __bfloat162float(__float2bfloat16(f.x));
            float hy = __bfloat162float(__float2bfloat16(f.y));
            float hz = __bfloat162float(__float2bfloat16(f.z));
            float hw = __bfloat162float(__float2bfloat16(f.w));
            uint2 h = make_uint2(pkbf(hx, hy), pkbf(hz, hw));
            uint2 l = make_uint2(pkbf(2.f * (f.x - hx), 2.f * (f.y - hy)),
                                 pkbf(2.f * (f.z - hz), 2.f * (f.w - hw)));
            size_t o = (size_t)p * N_FEAT + v * 4;
            *(uint2*)((char*)g_Xh + o * 2) = h;
            *(uint2*)((char*)g_Xl + o * 2) = l;
        }
        #pragma unroll
        for (int o = 16; o; o >>= 1) nrm += __shfl_xor_sync(0xffffffffu, nrm, o);
        if (lid == 0) { g_invn[p] = 1.f / nrm; g_sidp[p] = sids[i]; }
    }
}

// ---------------- launch 4: main MMA kernel ----------------
#define XPIT     144                     // 64 bf16 + 8 pad
#define APIT     272                     // 128 bf16 + 8 pad
#define XH_OFF   0
#define AH_OFF   (128 * XPIT)            // 18432
#define AL_OFF   (AH_OFF + 64 * APIT)    // 35840
#define BUFSZ    (AL_OFF + 64 * APIT)    // 53248
#define ESM_OFF  (2 * BUFSZ)             // 106496
#define SMEM_DYN (ESM_OFF + 512)

__global__ __launch_bounds__(256, 2) void k_main_mma(float* __restrict__ out) {
    extern __shared__ char smem[];
    const uint32_t sb = smem_u32(smem);
    float* esm = (float*)(smem + ESM_OFF);

    const int tid = threadIdx.x, wid = tid >> 5, lid = tid & 31;
    const int s = blockIdx.y;
    const int off0 = g_off[s], off1 = g_off[s + 1];
    const int base = off0 + blockIdx.x * MT;
    if (base >= off1) return;
    const int valid = min(MT, off1 - base);

    if (tid < MT) esm[tid] = 0.f;

    const int mg = wid >> 2;     // 0..1 : 64 rows each
    const int ng = wid & 3;      // 0..3 : 32 cols each

    const int xrow = (lid & 7) + ((lid >> 3) & 1) * 8;
    const int xkof = ((lid >> 4) & 1) * 8;
    const int akrow = (lid & 7) + ((lid >> 3) & 1) * 8;
    const int anof = ((lid >> 4) & 1) * 8;

    float er[4][2];
    #pragma unroll
    for (int a = 0; a < 4; ++a) { er[a][0] = 0.f; er[a][1] = 0.f; }

    for (int nc = 0; nc < N_FEAT / NC; ++nc) {
        float acc[4][4][4];
        #pragma unroll
        for (int a = 0; a < 4; ++a)
            #pragma unroll
            for (int b = 0; b < 4; ++b)
                #pragma unroll
                for (int q = 0; q < 4; ++q) acc[a][b][q] = 0.f;

        auto issue = [&](int kc) {
            uint32_t bufb = sb + (kc & 1) * BUFSZ;
            #pragma unroll
            for (int it = 0; it < 4; ++it) {
                int idx = it * 256 + tid;
                int r = idx >> 3, v = idx & 7;
                const char* src = (const char*)(g_Xh + (size_t)(base + r) * N_FEAT
                                                + kc * KC + v * 8);
                cpasync16(bufb + XH_OFF + r * XPIT + v * 16, src);
            }
            #pragma unroll
            for (int it = 0; it < 8; ++it) {
                int idx = it * 256 + tid;
                int sel = idx >> 10, e = idx & 1023;
                int r = e >> 4, v = e & 15;
                const __nv_bfloat16* g = sel ? g_Al : g_Ah;
                const char* src = (const char*)(g + ((size_t)s * N_FEAT + kc * KC + r) * N_FEAT
                                                + nc * NC + v * 8);
                cpasync16(bufb + (sel ? AL_OFF : AH_OFF) + r * APIT + v * 16, src);
            }
        };

        issue(0); CP_COMMIT();

        for (int kc = 0; kc < N_FEAT / KC; ++kc) {
            if (kc + 1 < N_FEAT / KC) {
                issue(kc + 1); CP_COMMIT();
                asm volatile("cp.async.wait_group 1;" ::: "memory");
            } else {
                asm volatile("cp.async.wait_group 0;" ::: "memory");
            }
            __syncthreads();

            const uint32_t bufb = sb + (kc & 1) * BUFSZ;
            #pragma unroll
            for (int ks = 0; ks < KC / 16; ++ks) {
                uint32_t bh[2][4], bl[2][4];
                #pragma unroll
                for (int t = 0; t < 2; ++t) {
                    uint32_t aa = bufb + AH_OFF + (ks * 16 + akrow) * APIT
                                + (ng * 32 + t * 16 + anof) * 2;
                    ldsm_x4t(bh[t], aa);
                    ldsm_x4t(bl[t], aa + (AL_OFF - AH_OFF));
                }
                uint32_t xa[4][4];
                #pragma unroll
                for (int mt = 0; mt < 4; ++mt) {
                    uint32_t xaddr = bufb + XH_OFF + (mg * 64 + mt * 16 + xrow) * XPIT
                                   + (ks * 16 + xkof) * 2;
                    ldsm_x4(xa[mt], xaddr);
                }
                #pragma unroll
                for (int mt = 0; mt < 4; ++mt)
                    #pragma unroll
                    for (int nt = 0; nt < 4; ++nt) {
                        mma16816(acc[mt][nt], xa[mt], &bh[nt >> 1][(nt & 1) * 2]);
                        mma16816(acc[mt][nt], xa[mt], &bl[nt >> 1][(nt & 1) * 2]);
                    }
            }
            __syncthreads();
        }

        // fold Q .* (xh + 2xl) into register partials (atomics deferred)
        #pragma unroll
        for (int mt = 0; mt < 4; ++mt) {
            int r0 = base + mg * 64 + mt * 16 + (lid >> 2);
            #pragma unroll
            for (int nt = 0; nt < 4; ++nt) {
                int j = nc * NC + ng * 32 + nt * 8 + (lid & 3) * 2;
                size_t o0 = (size_t)r0 * N_FEAT + j;
                size_t o1 = o0 + 8 * N_FEAT;
                float2 h0 = __bfloat1622float2(*(const __nv_bfloat162*)((const char*)g_Xh + o0 * 2));
                float2 l0 = __bfloat1622float2(*(const __nv_bfloat162*)((const char*)g_Xl + o0 * 2));
                float2 h1 = __bfloat1622float2(*(const __nv_bfloat162*)((const char*)g_Xh + o1 * 2));
                float2 l1 = __bfloat1622float2(*(const __nv_bfloat162*)((const char*)g_Xl + o1 * 2));
                er[mt][0] += acc[mt][nt][0] * (h0.x + l0.x) + acc[mt][nt][1] * (h0.y + l0.y);
                er[mt][1] += acc[mt][nt][2] * (h1.x + l1.x) + acc[mt][nt][3] * (h1.y + l1.y);
            }
        }
    }

    // quad-lane reduce, single smem atomic per row partial
    #pragma unroll
    for (int mt = 0; mt < 4; ++mt)
        #pragma unroll
        for (int hh = 0; hh < 2; ++hh) {
            float v = er[mt][hh];
            v += __shfl_xor_sync(0xffffffffu, v, 1);
            v += __shfl_xor_sync(0xffffffffu, v, 2);
            if ((lid & 3) == 0)
                atomicAdd(&esm[mg * 64 + mt * 16 + (lid >> 2) + hh * 8], v);
        }
    __syncthreads();

    if (tid < valid) {
        int p = base + tid;
        atomicAdd(&out[g_sidp[p]], esm[tid] * g_invn[p]);
    }
}

// ---------------- launch ----------------
extern "C" void kernel_launch(void* const* d_in, const int* in_sizes, int n_in,
                              void* d_out, int out_size) {
    const float* ps   = (const float*)d_in[0];
    const float* sp   = (const float*)d_in[1];
    const float* w    = (const float*)d_in[2];
    const int*   spec = (const int*)d_in[3];
    const int*   sids = (const int*)d_in[4];
    float* out = (float*)d_out;

    int n_atoms   = in_sizes[3];
    int n_support = in_sizes[2] / N_SPECIES;

    cudaFuncSetAttribute(k_main_mma, cudaFuncAttributeMaxDynamicSharedMemorySize, SMEM_DYN);

    int pb = (N_SPECIES * n_support + 3) / 4;
    int cb = (n_atoms + 511) / 512;
    k_fuse1<<<pb + cb, 512>>>(sp, w, n_support, spec, n_atoms, out, out_size, pb);
    k_off<<<1, 32>>>();
    int sxb = (n_atoms + 15) / 16;
    k_fuse2<<<36 * N_SPECIES + sxb, 512>>>(sp, n_support, ps, spec, sids, n_atoms);

    dim3 grid((n_atoms + MT - 1) / MT, N_SPECIES);
    k_main_mma<<<grid, 256, SMEM_DYN>>>(out);
}

// round 8
// speedup vs baseline: 1.0001x; 1.0001x over previous
#include <cuda_runtime.h>
#include <cuda_bf16.h>
#include <stdint.h>

// SparseGapPerSpecies: quadratic form + warp bf16 MMA, symmetry-reduced.
//   A_s = Y_s^T diag(w/|y|^2) Y_s (symmetric) -> bf16 hi+lo
//   x'Ax = xh'A(xh+2xl) + O(2^-16)  => Q = Xh*(Ah+Al): 2 GEMM terms
//   e_atom = rowdot(Q, xh + 2xl)/|x|^2 ; energy = segment_sum
// Launch plan (ncu profiles launch #4): fuse1, off, fuse2, MAIN.

#define N_SPECIES   4
#define N_FEAT      512
#define MAX_ATOMS   100352
#define MAX_SUPPORT 1024
#define MT          128
#define NC          128
#define KC          64

__device__ __nv_bfloat16 g_Ah[N_SPECIES * N_FEAT * N_FEAT];  // [s][k][n]
__device__ __nv_bfloat16 g_Al[N_SPECIES * N_FEAT * N_FEAT];
__device__ __nv_bfloat16 g_Xh[(size_t)MAX_ATOMS * N_FEAT];   // sorted by species
__device__ __nv_bfloat16 g_Xl[(size_t)MAX_ATOMS * N_FEAT];   // holds 2*xl
__device__ float g_invn[MAX_ATOMS];
__device__ int   g_sidp[MAX_ATOMS];
__device__ float g_c[N_SPECIES * MAX_SUPPORT];
__device__ int   g_cnt[N_SPECIES];        // zero-init; k_off resets after use
__device__ int   g_off[N_SPECIES + 1];
__device__ int   g_cur[N_SPECIES];

// ---------------- PTX helpers ----------------
__device__ __forceinline__ uint32_t smem_u32(const void* p) {
    uint32_t a;
    asm("{ .reg .u64 t; cvta.to.shared.u64 t, %1; cvt.u32.u64 %0, t; }" : "=r"(a) : "l"(p));
    return a;
}
__device__ __forceinline__ void cpasync16(uint32_t dst, const void* src) {
    asm volatile("cp.async.cg.shared.global [%0], [%1], 16;" :: "r"(dst), "l"(src) : "memory");
}
#define CP_COMMIT() asm volatile("cp.async.commit_group;" ::: "memory")

__device__ __forceinline__ void ldsm_x4(uint32_t* r, uint32_t a) {
    asm volatile("ldmatrix.sync.aligned.m8n8.x4.shared.b16 {%0,%1,%2,%3}, [%4];"
                 : "=r"(r[0]), "=r"(r[1]), "=r"(r[2]), "=r"(r[3]) : "r"(a));
}
__device__ __forceinline__ void ldsm_x4t(uint32_t* r, uint32_t a) {
    asm volatile("ldmatrix.sync.aligned.m8n8.x4.trans.shared.b16 {%0,%1,%2,%3}, [%4];"
                 : "=r"(r[0]), "=r"(r[1]), "=r"(r[2]), "=r"(r[3]) : "r"(a));
}
__device__ __forceinline__ void mma16816(float* c, const uint32_t* a, const uint32_t* b) {
    asm volatile("mma.sync.aligned.m16n8k16.row.col.f32.bf16.bf16.f32 "
                 "{%0,%1,%2,%3},{%4,%5,%6,%7},{%8,%9},{%0,%1,%2,%3};"
                 : "+f"(c[0]), "+f"(c[1]), "+f"(c[2]), "+f"(c[3])
                 : "r"(a[0]), "r"(a[1]), "r"(a[2]), "r"(a[3]), "r"(b[0]), "r"(b[1]));
}
__device__ __forceinline__ uint32_t pkbf(float a, float b) {
    __nv_bfloat162 t = __floats2bfloat162_rn(a, b);
    return *(uint32_t*)&t;
}

// ---------------- launch 1: prep_c (4 pts/block) || countz ----------------
__global__ __launch_bounds__(512) void k_fuse1(const float* __restrict__ sp,
                                               const float* __restrict__ w,
                                               int n_support,
                                               const int* __restrict__ spc, int n,
                                               float* out, int n_out, int pb) {
    int bx = blockIdx.x;
    if (bx < pb) {
        // prep_c: 4 support points per block, 128 threads each
        __shared__ float r[4][4];
        int g = threadIdx.x >> 7, st = threadIdx.x & 127;
        int pt = bx * 4 + g;
        int total = N_SPECIES * n_support;
        float acc = 0.f;
        if (pt < total) {
            const float* y = sp + (size_t)pt * N_FEAT;
            #pragma unroll
            for (int t = 0; t < 4; ++t) { float v = y[st + t * 128]; acc += v * v; }
        }
        #pragma unroll
        for (int o = 16; o; o >>= 1) acc += __shfl_xor_sync(0xffffffffu, acc, o);
        if ((st & 31) == 0) r[g][st >> 5] = acc;
        __syncthreads();
        if (st == 0 && pt < total) {
            int s = pt / n_support, m = pt % n_support;
            g_c[s * MAX_SUPPORT + m] = w[pt] / (r[g][0] + r[g][1] + r[g][2] + r[g][3]);
        }
    } else {
        int i = (bx - pb) * 512 + threadIdx.x;
        if (i < n) atomicAdd(&g_cnt[spc[i]], 1);
        if (i < n_out) out[i] = 0.f;
    }
}

// ---------------- launch 2: offsets (+ reset counters for replay) ----------------
__global__ void k_off() {
    if (threadIdx.x == 0) {
        int acc = 0;
        for (int s = 0; s < N_SPECIES; ++s) {
            g_off[s] = acc; g_cur[s] = acc; acc += g_cnt[s]; g_cnt[s] = 0;
        }
        g_off[N_SPECIES] = acc;
    }
}

// ---------------- launch 3: computeA (144 blocks) || scatterX ----------------
__global__ __launch_bounds__(512) void k_fuse2(const float* __restrict__ sp, int n_support,
                                               const float* __restrict__ ps,
                                               const int* __restrict__ spc,
                                               const int* __restrict__ sids, int n) {
    int bx = blockIdx.x;
    if (bx < 36 * N_SPECIES) {
        // ---- computeA: A = Y' diag(c) Y, upper-tri 64x64 tile + mirror ----
        __shared__ float Yi[16][64];
        __shared__ float Yj[16][64];
        int s = bx / 36;
        int t = bx % 36;
        int bi = 0;
        { int rowlen = 8; while (t >= rowlen) { t -= rowlen; rowlen--; bi++; } }
        int bj = bi + t;
        int i0 = bi * 64, j0 = bj * 64;

        int tid = threadIdx.x;
        int ty = tid >> 4, tx = tid & 15;     // 32 x 16 threads, 2x4 acc
        float acc[2][4];
        #pragma unroll
        for (int a = 0; a < 2; ++a)
            #pragma unroll
            for (int b = 0; b < 4; ++b) acc[a][b] = 0.f;

        const float* Y = sp + (size_t)s * n_support * N_FEAT;
        const float* c = g_c + s * MAX_SUPPORT;

        for (int m0 = 0; m0 < n_support; m0 += 16) {
            #pragma unroll
            for (int it = 0; it < 2; ++it) {
                int idx = it * 512 + tid;
                int kk = idx >> 6, col = idx & 63;
                int m = m0 + kk;
                float yi = 0.f, yj = 0.f, cm = 0.f;
                if (m < n_support) {
                    cm = c[m];
                    yi = Y[(size_t)m * N_FEAT + i0 + col];
                    yj = Y[(size_t)m * N_FEAT + j0 + col];
                }
                Yi[kk][col] = cm * yi;
                Yj[kk][col] = yj;
            }
            __syncthreads();
            #pragma unroll
            for (int kk = 0; kk < 16; ++kk) {
                float a0 = Yi[kk][ty * 2], a1 = Yi[kk][ty * 2 + 1];
                float b[4];
                #pragma unroll
                for (int jj = 0; jj < 4; ++jj) b[jj] = Yj[kk][tx * 4 + jj];
                #pragma unroll
                for (int jj = 0; jj < 4; ++jj) { acc[0][jj] += a0 * b[jj]; acc[1][jj] += a1 * b[jj]; }
            }
            __syncthreads();
        }
        #pragma unroll
        for (int ii = 0; ii < 2; ++ii)
            #pragma unroll
            for (int jj = 0; jj < 4; ++jj) {
                int i = i0 + ty * 2 + ii;
                int j = j0 + tx * 4 + jj;
                float a = acc[ii][jj];
                __nv_bfloat16 h = __float2bfloat16(a);
                __nv_bfloat16 l = __float2bfloat16(a - __bfloat162float(h));
                size_t o = ((size_t)s * N_FEAT + i) * N_FEAT + j;
                g_Ah[o] = h; g_Al[o] = l;
                if (bi != bj) {
                    size_t om = ((size_t)s * N_FEAT + j) * N_FEAT + i;
                    g_Ah[om] = h; g_Al[om] = l;
                }
            }
    } else {
        // ---- scatterX: warp per atom; store xh and 2*xl; 1/|x|^2; sid ----
        int wid = threadIdx.x >> 5, lid = threadIdx.x & 31;
        int i = (bx - 36 * N_SPECIES) * 16 + wid;
        if (i >= n) return;
        int p;
        if (lid == 0) p = atomicAdd(&g_cur[spc[i]], 1);
        p = __shfl_sync(0xffffffffu, p, 0);

        const float4* src = (const float4*)(ps + (size_t)i * N_FEAT);
        float nrm = 0.f;
        #pragma unroll
        for (int t = 0; t < 4; ++t) {
            int v = lid + t * 32;
            float4 f = __ldg(src + v);
            nrm += f.x * f.x + f.y * f.y + f.z * f.z + f.w * f.w;
            float hx = __bfloat162float(__float2bfloat16(f.x));
            float hy = __bfloat162float(__float2bfloat16(f.y));
            float hz = __bfloat162float(__float2bfloat16(f.z));
            float hw = __bfloat162float(__float2bfloat16(f.w));
            uint2 h = make_uint2(pkbf(hx, hy), pkbf(hz, hw));
            uint2 l = make_uint2(pkbf(2.f * (f.x - hx), 2.f * (f.y - hy)),
                                 pkbf(2.f * (f.z - hz), 2.f * (f.w - hw)));
            size_t o = (size_t)p * N_FEAT + v * 4;
            *(uint2*)((char*)g_Xh + o * 2) = h;
            *(uint2*)((char*)g_Xl + o * 2) = l;
        }
        #pragma unroll
        for (int o = 16; o; o >>= 1) nrm += __shfl_xor_sync(0xffffffffu, nrm, o);
        if (lid == 0) { g_invn[p] = 1.f / nrm; g_sidp[p] = sids[i]; }
    }
}

// ---------------- launch 4: main MMA kernel ----------------
#define XPIT     144                     // 64 bf16 + 8 pad
#define APIT     272                     // 128 bf16 + 8 pad
#define XH_OFF   0
#define AH_OFF   (128 * XPIT)            // 18432
#define AL_OFF   (AH_OFF + 64 * APIT)    // 35840
#define BUFSZ    (AL_OFF + 64 * APIT)    // 53248
#define ESM_OFF  (2 * BUFSZ)             // 106496
#define SMEM_DYN (ESM_OFF + 512)

__global__ __launch_bounds__(256, 2) void k_main_mma(float* __restrict__ out) {
    extern __shared__ char smem[];
    const uint32_t sb = smem_u32(smem);
    float* esm = (float*)(smem + ESM_OFF);

    const int tid = threadIdx.x, wid = tid >> 5, lid = tid & 31;
    const int s = blockIdx.y;
    const int off0 = g_off[s], off1 = g_off[s + 1];
    const int base = off0 + blockIdx.x * MT;
    if (base >= off1) return;
    const int valid = min(MT, off1 - base);

    if (tid < MT) esm[tid] = 0.f;

    const int mg = wid >> 2;     // 0..1 : 64 rows each
    const int ng = wid & 3;      // 0..3 : 32 cols each

    const int xrow = (lid & 7) + ((lid >> 3) & 1) * 8;
    const int xkof = ((lid >> 4) & 1) * 8;
    const int akrow = (lid & 7) + ((lid >> 3) & 1) * 8;
    const int anof = ((lid >> 4) & 1) * 8;

    float er[4][2];
    #pragma unroll
    for (int a = 0; a < 4; ++a) { er[a][0] = 0.f; er[a][1] = 0.f; }

    for (int nc = 0; nc < N_FEAT / NC; ++nc) {
        float acc[4][4][4];
        #pragma unroll
        for (int a = 0; a < 4; ++a)
            #pragma unroll
            for (int b = 0; b < 4; ++b)
                #pragma unroll
                for (int q = 0; q < 4; ++q) acc[a][b][q] = 0.f;

        auto issue = [&](int kc) {
            uint32_t bufb = sb + (kc & 1) * BUFSZ;
            #pragma unroll
            for (int it = 0; it < 4; ++it) {
                int idx = it * 256 + tid;
                int r = idx >> 3, v = idx & 7;
                const char* src = (const char*)(g_Xh + (size_t)(base + r) * N_FEAT
                                                + kc * KC + v * 8);
                cpasync16(bufb + XH_OFF + r * XPIT + v * 16, src);
            }
            #pragma unroll
            for (int it = 0; it < 8; ++it) {
                int idx = it * 256 + tid;
                int sel = idx >> 10, e = idx & 1023;
                int r = e >> 4, v = e & 15;
                const __nv_bfloat16* g = sel ? g_Al : g_Ah;
                const char* src = (const char*)(g + ((size_t)s * N_FEAT + kc * KC + r) * N_FEAT
                                                + nc * NC + v * 8);
                cpasync16(bufb + (sel ? AL_OFF : AH_OFF) + r * APIT + v * 16, src);
            }
        };

        issue(0); CP_COMMIT();

        for (int kc = 0; kc < N_FEAT / KC; ++kc) {
            if (kc + 1 < N_FEAT / KC) {
                issue(kc + 1); CP_COMMIT();
                asm volatile("cp.async.wait_group 1;" ::: "memory");
            } else {
                asm volatile("cp.async.wait_group 0;" ::: "memory");
            }
            __syncthreads();

            const uint32_t bufb = sb + (kc & 1) * BUFSZ;
            #pragma unroll
            for (int ks = 0; ks < KC / 16; ++ks) {
                uint32_t bh[2][4], bl[2][4];
                #pragma unroll
                for (int t = 0; t < 2; ++t) {
                    uint32_t aa = bufb + AH_OFF + (ks * 16 + akrow) * APIT
                                + (ng * 32 + t * 16 + anof) * 2;
                    ldsm_x4t(bh[t], aa);
                    ldsm_x4t(bl[t], aa + (AL_OFF - AH_OFF));
                }
                uint32_t xa[4][4];
                #pragma unroll
                for (int mt = 0; mt < 4; ++mt) {
                    uint32_t xaddr = bufb + XH_OFF + (mg * 64 + mt * 16 + xrow) * XPIT
                                   + (ks * 16 + xkof) * 2;
                    ldsm_x4(xa[mt], xaddr);
                }
                #pragma unroll
                for (int mt = 0; mt < 4; ++mt)
                    #pragma unroll
                    for (int nt = 0; nt < 4; ++nt) {
                        mma16816(acc[mt][nt], xa[mt], &bh[nt >> 1][(nt & 1) * 2]);
                        mma16816(acc[mt][nt], xa[mt], &bl[nt >> 1][(nt & 1) * 2]);
                    }
            }
            __syncthreads();
        }

        // fold Q .* (xh + 2xl) into register partials (atomics deferred)
        #pragma unroll
        for (int mt = 0; mt < 4; ++mt) {
            int r0 = base + mg * 64 + mt * 16 + (lid >> 2);
            #pragma unroll
            for (int nt = 0; nt < 4; ++nt) {
                int j = nc * NC + ng * 32 + nt * 8 + (lid & 3) * 2;
                size_t o0 = (size_t)r0 * N_FEAT + j;
                size_t o1 = o0 + 8 * N_FEAT;
                float2 h0 = __bfloat1622float2(*(const __nv_bfloat162*)((const char*)g_Xh + o0 * 2));
                float2 l0 = __bfloat1622float2(*(const __nv_bfloat162*)((const char*)g_Xl + o0 * 2));
                float2 h1 = __bfloat1622float2(*(const __nv_bfloat162*)((const char*)g_Xh + o1 * 2));
                float2 l1 = __bfloat1622float2(*(const __nv_bfloat162*)((const char*)g_Xl + o1 * 2));
                er[mt][0] += acc[mt][nt][0] * (h0.x + l0.x) + acc[mt][nt][1] * (h0.y + l0.y);
                er[mt][1] += acc[mt][nt][2] * (h1.x + l1.x) + acc[mt][nt][3] * (h1.y + l1.y);
            }
        }
    }

    // quad-lane reduce, single smem atomic per row partial
    #pragma unroll
    for (int mt = 0; mt < 4; ++mt)
        #pragma unroll
        for (int hh = 0; hh < 2; ++hh) {
            float v = er[mt][hh];
            v += __shfl_xor_sync(0xffffffffu, v, 1);
            v += __shfl_xor_sync(0xffffffffu, v, 2);
            if ((lid & 3) == 0)
                atomicAdd(&esm[mg * 64 + mt * 16 + (lid >> 2) + hh * 8], v);
        }
    __syncthreads();

    if (tid < valid) {
        int p = base + tid;
        atomicAdd(&out[g_sidp[p]], esm[tid] * g_invn[p]);
    }
}

// ---------------- launch ----------------
extern "C" void kernel_launch(void* const* d_in, const int* in_sizes, int n_in,
                              void* d_out, int out_size) {
    const float* ps   = (const float*)d_in[0];
    const float* sp   = (const float*)d_in[1];
    const float* w    = (const float*)d_in[2];
    const int*   spec = (const int*)d_in[3];
    const int*   sids = (const int*)d_in[4];
    float* out = (float*)d_out;

    int n_atoms   = in_sizes[3];
    int n_support = in_sizes[2] / N_SPECIES;

    cudaFuncSetAttribute(k_main_mma, cudaFuncAttributeMaxDynamicSharedMemorySize, SMEM_DYN);

    int pb = (N_SPECIES * n_support + 3) / 4;
    int cb = (n_atoms + 511) / 512;
    k_fuse1<<<pb + cb, 512>>>(sp, w, n_support, spec, n_atoms, out, out_size, pb);
    k_off<<<1, 32>>>();
    int sxb = (n_atoms + 15) / 16;
    k_fuse2<<<36 * N_SPECIES + sxb, 512>>>(sp, n_support, ps, spec, sids, n_atoms);

    dim3 grid((n_atoms + MT - 1) / MT, N_SPECIES);
    k_main_mma<<<grid, 256, SMEM_DYN>>>(out);
}

// round 9
// speedup vs baseline: 1.0029x; 1.0028x over previous
#include <cuda_runtime.h>
#include <cuda_bf16.h>
#include <stdint.h>

// SparseGapPerSpecies: quadratic form + warp bf16 MMA, symmetry-reduced.
//   A_s = Y_s^T diag(w/|y|^2) Y_s (symmetric) -> bf16 hi+lo
//   x'Ax = xh'A(xh+2xl) + O(2^-16)  => Q = Xh*(Ah+Al): 2 GEMM terms
//   e_atom = rowdot(Q, xh + 2xl)/|x|^2 ; energy = segment_sum
// Launch plan (ncu profiles launch #4): fuse1, off, fuse2, MAIN.

#define N_SPECIES   4
#define N_FEAT      512
#define MAX_ATOMS   100352
#define MAX_SUPPORT 1024
#define MT          128
#define NC          128
#define KC          64

__device__ __nv_bfloat16 g_Ah[N_SPECIES * N_FEAT * N_FEAT];  // [s][k][n]
__device__ __nv_bfloat16 g_Al[N_SPECIES * N_FEAT * N_FEAT];
__device__ __nv_bfloat16 g_Xh[(size_t)MAX_ATOMS * N_FEAT];   // sorted by species
__device__ __nv_bfloat16 g_Xl[(size_t)MAX_ATOMS * N_FEAT];   // holds 2*xl
__device__ float g_invn[MAX_ATOMS];
__device__ int   g_sidp[MAX_ATOMS];
__device__ float g_c[N_SPECIES * MAX_SUPPORT];
__device__ int   g_cnt[N_SPECIES];        // zero-init; k_off resets after use
__device__ int   g_off[N_SPECIES + 1];
__device__ int   g_cur[N_SPECIES];

// ---------------- PTX helpers ----------------
__device__ __forceinline__ uint32_t smem_u32(const void* p) {
    uint32_t a;
    asm("{ .reg .u64 t; cvta.to.shared.u64 t, %1; cvt.u32.u64 %0, t; }" : "=r"(a) : "l"(p));
    return a;
}
__device__ __forceinline__ void cpasync16(uint32_t dst, const void* src) {
    asm volatile("cp.async.cg.shared.global [%0], [%1], 16;" :: "r"(dst), "l"(src) : "memory");
}
#define CP_COMMIT() asm volatile("cp.async.commit_group;" ::: "memory")

__device__ __forceinline__ void ldsm_x4(uint32_t* r, uint32_t a) {
    asm volatile("ldmatrix.sync.aligned.m8n8.x4.shared.b16 {%0,%1,%2,%3}, [%4];"
                 : "=r"(r[0]), "=r"(r[1]), "=r"(r[2]), "=r"(r[3]) : "r"(a));
}
__device__ __forceinline__ void ldsm_x4t(uint32_t* r, uint32_t a) {
    asm volatile("ldmatrix.sync.aligned.m8n8.x4.trans.shared.b16 {%0,%1,%2,%3}, [%4];"
                 : "=r"(r[0]), "=r"(r[1]), "=r"(r[2]), "=r"(r[3]) : "r"(a));
}
__device__ __forceinline__ void mma16816(float* c, const uint32_t* a, const uint32_t* b) {
    asm volatile("mma.sync.aligned.m16n8k16.row.col.f32.bf16.bf16.f32 "
                 "{%0,%1,%2,%3},{%4,%5,%6,%7},{%8,%9},{%0,%1,%2,%3};"
                 : "+f"(c[0]), "+f"(c[1]), "+f"(c[2]), "+f"(c[3])
                 : "r"(a[0]), "r"(a[1]), "r"(a[2]), "r"(a[3]), "r"(b[0]), "r"(b[1]));
}
__device__ __forceinline__ uint32_t pkbf(float a, float b) {
    __nv_bfloat162 t = __floats2bfloat162_rn(a, b);
    return *(uint32_t*)&t;
}

// ---------------- launch 1: prep_c (4 pts/block) || countz ----------------
__global__ __launch_bounds__(512) void k_fuse1(const float* __restrict__ sp,
                                               const float* __restrict__ w,
                                               int n_support,
                                               const int* __restrict__ spc, int n,
                                               float* out, int n_out, int pb) {
    int bx = blockIdx.x;
    if (bx < pb) {
        // prep_c: 4 support points per block, 128 threads each
        __shared__ float r[4][4];
        int g = threadIdx.x >> 7, st = threadIdx.x & 127;
        int pt = bx * 4 + g;
        int total = N_SPECIES * n_support;
        float acc = 0.f;
        if (pt < total) {
            const float* y = sp + (size_t)pt * N_FEAT;
            #pragma unroll
            for (int t = 0; t < 4; ++t) { float v = y[st + t * 128]; acc += v * v; }
        }
        #pragma unroll
        for (int o = 16; o; o >>= 1) acc += __shfl_xor_sync(0xffffffffu, acc, o);
        if ((st & 31) == 0) r[g][st >> 5] = acc;
        __syncthreads();
        if (st == 0 && pt < total) {
            int s = pt / n_support, m = pt % n_support;
            g_c[s * MAX_SUPPORT + m] = w[pt] / (r[g][0] + r[g][1] + r[g][2] + r[g][3]);
        }
    } else {
        int i = (bx - pb) * 512 + threadIdx.x;
        if (i < n) atomicAdd(&g_cnt[spc[i]], 1);
        if (i < n_out) out[i] = 0.f;
    }
}

// ---------------- launch 2: offsets (+ reset counters for replay) ----------------
__global__ void k_off() {
    if (threadIdx.x == 0) {
        int acc = 0;
        for (int s = 0; s < N_SPECIES; ++s) {
            g_off[s] = acc; g_cur[s] = acc; acc += g_cnt[s]; g_cnt[s] = 0;
        }
        g_off[N_SPECIES] = acc;
    }
}

// ---------------- launch 3: computeA (144 blocks) || scatterX ----------------
__global__ __launch_bounds__(512) void k_fuse2(const float* __restrict__ sp, int n_support,
                                               const float* __restrict__ ps,
                                               const int* __restrict__ spc,
                                               const int* __restrict__ sids, int n) {
    int bx = blockIdx.x;
    if (bx < 36 * N_SPECIES) {
        // ---- computeA: A = Y' diag(c) Y, upper-tri 64x64 tile + mirror ----
        __shared__ float Yi[16][64];
        __shared__ float Yj[16][64];
        int s = bx / 36;
        int t = bx % 36;
        int bi = 0;
        { int rowlen = 8; while (t >= rowlen) { t -= rowlen; rowlen--; bi++; } }
        int bj = bi + t;
        int i0 = bi * 64, j0 = bj * 64;

        int tid = threadIdx.x;
        int ty = tid >> 4, tx = tid & 15;     // 32 x 16 threads, 2x4 acc
        float acc[2][4];
        #pragma unroll
        for (int a = 0; a < 2; ++a)
            #pragma unroll
            for (int b = 0; b < 4; ++b) acc[a][b] = 0.f;

        const float* Y = sp + (size_t)s * n_support * N_FEAT;
        const float* c = g_c + s * MAX_SUPPORT;

        for (int m0 = 0; m0 < n_support; m0 += 16) {
            #pragma unroll
            for (int it = 0; it < 2; ++it) {
                int idx = it * 512 + tid;
                int kk = idx >> 6, col = idx & 63;
                int m = m0 + kk;
                float yi = 0.f, yj = 0.f, cm = 0.f;
                if (m < n_support) {
                    cm = c[m];
                    yi = Y[(size_t)m * N_FEAT + i0 + col];
                    yj = Y[(size_t)m * N_FEAT + j0 + col];
                }
                Yi[kk][col] = cm * yi;
                Yj[kk][col] = yj;
            }
            __syncthreads();
            #pragma unroll
            for (int kk = 0; kk < 16; ++kk) {
                float a0 = Yi[kk][ty * 2], a1 = Yi[kk][ty * 2 + 1];
                float b[4];
                #pragma unroll
                for (int jj = 0; jj < 4; ++jj) b[jj] = Yj[kk][tx * 4 + jj];
                #pragma unroll
                for (int jj = 0; jj < 4; ++jj) { acc[0][jj] += a0 * b[jj]; acc[1][jj] += a1 * b[jj]; }
            }
            __syncthreads();
        }
        #pragma unroll
        for (int ii = 0; ii < 2; ++ii)
            #pragma unroll
            for (int jj = 0; jj < 4; ++jj) {
                int i = i0 + ty * 2 + ii;
                int j = j0 + tx * 4 + jj;
                float a = acc[ii][jj];
                __nv_bfloat16 h = __float2bfloat16(a);
                __nv_bfloat16 l = __float2bfloat16(a - __bfloat162float(h));
                size_t o = ((size_t)s * N_FEAT + i) * N_FEAT + j;
                g_Ah[o] = h; g_Al[o] = l;
                if (bi != bj) {
                    size_t om = ((size_t)s * N_FEAT + j) * N_FEAT + i;
                    g_Ah[om] = h; g_Al[om] = l;
                }
            }
    } else {
        // ---- scatterX: warp per atom; store xh and 2*xl; 1/|x|^2; sid ----
        int wid = threadIdx.x >> 5, lid = threadIdx.x & 31;
        int i = (bx - 36 * N_SPECIES) * 16 + wid;
        if (i >= n) return;
        int p;
        if (lid == 0) p = atomicAdd(&g_cur[spc[i]], 1);
        p = __shfl_sync(0xffffffffu, p, 0);

        const float4* src = (const float4*)(ps + (size_t)i * N_FEAT);
        float nrm = 0.f;
        #pragma unroll
        for (int t = 0; t < 4; ++t) {
            int v = lid + t * 32;
            float4 f = __ldg(src + v);
            nrm += f.x * f.x + f.y * f.y + f.z * f.z + f.w * f.w;
            float hx = __bfloat162float(__float2bfloat16(f.x));
            float hy = __bfloat162float(__float2bfloat16(f.y));
            float hz = __bfloat162float(__float2bfloat16(f.z));
            float hw = __bfloat162float(__float2bfloat16(f.w));
            uint2 h = make_uint2(pkbf(hx, hy), pkbf(hz, hw));
            uint2 l = make_uint2(pkbf(2.f * (f.x - hx), 2.f * (f.y - hy)),
                                 pkbf(2.f * (f.z - hz), 2.f * (f.w - hw)));
            size_t o = (size_t)p * N_FEAT + v * 4;
            *(uint2*)((char*)g_Xh + o * 2) = h;
            *(uint2*)((char*)g_Xl + o * 2) = l;
        }
        #pragma unroll
        for (int o = 16; o; o >>= 1) nrm += __shfl_xor_sync(0xffffffffu, nrm, o);
        if (lid == 0) { g_invn[p] = 1.f / nrm; g_sidp[p] = sids[i]; }
    }
}

// ---------------- launch 4: main MMA kernel ----------------
#define XPIT     144                     // 64 bf16 + 8 pad
#define APIT     272                     // 128 bf16 + 8 pad
#define XH_OFF   0
#define AH_OFF   (128 * XPIT)            // 18432
#define AL_OFF   (AH_OFF + 64 * APIT)    // 35840
#define BUFSZ    (AL_OFF + 64 * APIT)    // 53248
#define ESM_OFF  (2 * BUFSZ)             // 106496
#define SMEM_DYN (ESM_OFF + 512)

__global__ __launch_bounds__(256, 2) void k_main_mma(float* __restrict__ out) {
    extern __shared__ char smem[];
    const uint32_t sb = smem_u32(smem);
    float* esm = (float*)(smem + ESM_OFF);

    const int tid = threadIdx.x, wid = tid >> 5, lid = tid & 31;
    const int s = blockIdx.y;
    const int off0 = g_off[s], off1 = g_off[s + 1];
    const int base = off0 + blockIdx.x * MT;
    if (base >= off1) return;
    const int valid = min(MT, off1 - base);

    if (tid < MT) esm[tid] = 0.f;

    const int mg = wid >> 2;     // 0..1 : 64 rows each
    const int ng = wid & 3;      // 0..3 : 32 cols each

    const int xrow = (lid & 7) + ((lid >> 3) & 1) * 8;
    const int xkof = ((lid >> 4) & 1) * 8;
    const int akrow = (lid & 7) + ((lid >> 3) & 1) * 8;
    const int anof = ((lid >> 4) & 1) * 8;

    float er[4][2];
    #pragma unroll
    for (int a = 0; a < 4; ++a) { er[a][0] = 0.f; er[a][1] = 0.f; }

    for (int nc = 0; nc < N_FEAT / NC; ++nc) {
        float acc[4][4][4];
        #pragma unroll
        for (int a = 0; a < 4; ++a)
            #pragma unroll
            for (int b = 0; b < 4; ++b)
                #pragma unroll
                for (int q = 0; q < 4; ++q) acc[a][b][q] = 0.f;

        auto issue = [&](int kc) {
            uint32_t bufb = sb + (kc & 1) * BUFSZ;
            #pragma unroll
            for (int it = 0; it < 4; ++it) {
                int idx = it * 256 + tid;
                int r = idx >> 3, v = idx & 7;
                const char* src = (const char*)(g_Xh + (size_t)(base + r) * N_FEAT
                                                + kc * KC + v * 8);
                cpasync16(bufb + XH_OFF + r * XPIT + v * 16, src);
            }
            #pragma unroll
            for (int it = 0; it < 8; ++it) {
                int idx = it * 256 + tid;
                int sel = idx >> 10, e = idx & 1023;
                int r = e >> 4, v = e & 15;
                const __nv_bfloat16* g = sel ? g_Al : g_Ah;
                const char* src = (const char*)(g + ((size_t)s * N_FEAT + kc * KC + r) * N_FEAT
                                                + nc * NC + v * 8);
                cpasync16(bufb + (sel ? AL_OFF : AH_OFF) + r * APIT + v * 16, src);
            }
        };

        issue(0); CP_COMMIT();

        for (int kc = 0; kc < N_FEAT / KC; ++kc) {
            if (kc + 1 < N_FEAT / KC) {
                issue(kc + 1); CP_COMMIT();
                asm volatile("cp.async.wait_group 1;" ::: "memory");
            } else {
                asm volatile("cp.async.wait_group 0;" ::: "memory");
            }
            __syncthreads();

            const uint32_t bufb = sb + (kc & 1) * BUFSZ;
            #pragma unroll
            for (int ks = 0; ks < KC / 16; ++ks) {
                uint32_t bh[2][4], bl[2][4];
                #pragma unroll
                for (int t = 0; t < 2; ++t) {
                    uint32_t aa = bufb + AH_OFF + (ks * 16 + akrow) * APIT
                                + (ng * 32 + t * 16 + anof) * 2;
                    ldsm_x4t(bh[t], aa);
                    ldsm_x4t(bl[t], aa + (AL_OFF - AH_OFF));
                }
                uint32_t xa[4][4];
                #pragma unroll
                for (int mt = 0; mt < 4; ++mt) {
                    uint32_t xaddr = bufb + XH_OFF + (mg * 64 + mt * 16 + xrow) * XPIT
                                   + (ks * 16 + xkof) * 2;
                    ldsm_x4(xa[mt], xaddr);
                }
                #pragma unroll
                for (int mt = 0; mt < 4; ++mt)
                    #pragma unroll
                    for (int nt = 0; nt < 4; ++nt) {
                        mma16816(acc[mt][nt], xa[mt], &bh[nt >> 1][(nt & 1) * 2]);
                        mma16816(acc[mt][nt], xa[mt], &bl[nt >> 1][(nt & 1) * 2]);
                    }
            }
            __syncthreads();
        }

        // fold Q .* (xh + 2xl) into register partials (atomics deferred)
        #pragma unroll
        for (int mt = 0; mt < 4; ++mt) {
            int r0 = base + mg * 64 + mt * 16 + (lid >> 2);
            #pragma unroll
            for (int nt = 0; nt < 4; ++nt) {
                int j = nc * NC + ng * 32 + nt * 8 + (lid & 3) * 2;
                size_t o0 = (size_t)r0 * N_FEAT + j;
                size_t o1 = o0 + 8 * N_FEAT;
                float2 h0 = __bfloat1622float2(*(const __nv_bfloat162*)((const char*)g_Xh + o0 * 2));
                float2 l0 = __bfloat1622float2(*(const __nv_bfloat162*)((const char*)g_Xl + o0 * 2));
                float2 h1 = __bfloat1622float2(*(const __nv_bfloat162*)((const char*)g_Xh + o1 * 2));
                float2 l1 = __bfloat1622float2(*(const __nv_bfloat162*)((const char*)g_Xl + o1 * 2));
                er[mt][0] += acc[mt][nt][0] * (h0.x + l0.x) + acc[mt][nt][1] * (h0.y + l0.y);
                er[mt][1] += acc[mt][nt][2] * (h1.x + l1.x) + acc[mt][nt][3] * (h1.y + l1.y);
            }
        }
    }

    // quad-lane reduce, single smem atomic per row partial
    #pragma unroll
    for (int mt = 0; mt < 4; ++mt)
        #pragma unroll
        for (int hh = 0; hh < 2; ++hh) {
            float v = er[mt][hh];
            v += __shfl_xor_sync(0xffffffffu, v, 1);
            v += __shfl_xor_sync(0xffffffffu, v, 2);
            if ((lid & 3) == 0)
                atomicAdd(&esm[mg * 64 + mt * 16 + (lid >> 2) + hh * 8], v);
        }
    __syncthreads();

    if (tid < valid) {
        int p = base + tid;
        atomicAdd(&out[g_sidp[p]], esm[tid] * g_invn[p]);
    }
}

// ---------------- launch ----------------
extern "C" void kernel_launch(void* const* d_in, const int* in_sizes, int n_in,
                              void* d_out, int out_size) {
    const float* ps   = (const float*)d_in[0];
    const float* sp   = (const float*)d_in[1];
    const float* w    = (const float*)d_in[2];
    const int*   spec = (const int*)d_in[3];
    const int*   sids = (const int*)d_in[4];
    float* out = (float*)d_out;

    int n_atoms   = in_sizes[3];
    int n_support = in_sizes[2] / N_SPECIES;

    cudaFuncSetAttribute(k_main_mma, cudaFuncAttributeMaxDynamicSharedMemorySize, SMEM_DYN);

    int pb = (N_SPECIES * n_support + 3) / 4;
    int cb = (n_atoms + 511) / 512;
    k_fuse1<<<pb + cb, 512>>>(sp, w, n_support, spec, n_atoms, out, out_size, pb);
    k_off<<<1, 32>>>();
    int sxb = (n_atoms + 15) / 16;
    k_fuse2<<<36 * N_SPECIES + sxb, 512>>>(sp, n_support, ps, spec, sids, n_atoms);

    dim3 grid((n_atoms + MT - 1) / MT, N_SPECIES);
    k_main_mma<<<grid, 256, SMEM_DYN>>>(out);
}